// round 5
// baseline (speedup 1.0000x reference)
#include <cuda_runtime.h>
#include <cuda_bf16.h>
#include <math.h>
#include <stdint.h>

#define N_TOK 16384
#define D_DIM 1024
#define N_EXP 64
#define CAPACITY 640
#define CHUNK 256
#define NCHUNK (N_TOK / CHUNK)   // 64

#define KB 32                    // k per pipeline chunk
#define NCHUNKS_K (D_DIM / KB)   // 32

// ---------------- scratch (static device globals; no runtime alloc) ----------
__device__ int   g_topidx[N_TOK * 2];
__device__ float g_gates [N_TOK * 2];
__device__ int   g_cnt   [N_EXP];
__device__ int   g_slot  [N_TOK * 2];
__device__ int   g_toklist[N_EXP * CAPACITY];
__device__ float g_ybuf[(size_t)N_TOK * 2 * D_DIM];

__device__ __nv_bfloat16 g_xhi[(size_t)N_TOK * D_DIM];
__device__ __nv_bfloat16 g_xlo[(size_t)N_TOK * D_DIM];
// B planes, K-major: B[e][n][k] = We[e][k][n]
__device__ __nv_bfloat16 g_Bhi[(size_t)N_EXP * D_DIM * D_DIM];
__device__ __nv_bfloat16 g_Blo[(size_t)N_EXP * D_DIM * D_DIM];

// ---------------- ptx helpers -------------------------------------------------
__device__ __forceinline__ uint32_t smem_u32(const void* p) {
    uint32_t a;
    asm("{ .reg .u64 t; cvta.to.shared.u64 t, %1; cvt.u32.u64 %0, t; }" : "=r"(a) : "l"(p));
    return a;
}
#define CP_ASYNC16(dst, src) \
    asm volatile("cp.async.cg.shared.global [%0], [%1], 16;" :: "r"(dst), "l"(src))
#define CP_COMMIT() asm volatile("cp.async.commit_group;" ::: "memory")
#define CP_WAIT1()  asm volatile("cp.async.wait_group 1;" ::: "memory")
#define CP_WAIT0()  asm volatile("cp.async.wait_group 0;" ::: "memory")

__device__ __forceinline__ void ldsm4(uint32_t* r, uint32_t addr) {
    asm volatile("ldmatrix.sync.aligned.m8n8.x4.shared.b16 {%0,%1,%2,%3}, [%4];"
        : "=r"(r[0]), "=r"(r[1]), "=r"(r[2]), "=r"(r[3]) : "r"(addr));
}
__device__ __forceinline__ void mma16816(float* d, const uint32_t* a,
                                         const uint32_t* b) {
    asm volatile("mma.sync.aligned.m16n8k16.row.col.f32.bf16.bf16.f32 "
        "{%0,%1,%2,%3}, {%4,%5,%6,%7}, {%8,%9}, {%0,%1,%2,%3};"
        : "+f"(d[0]), "+f"(d[1]), "+f"(d[2]), "+f"(d[3])
        : "r"(a[0]), "r"(a[1]), "r"(a[2]), "r"(a[3]), "r"(b[0]), "r"(b[1]));
}

// ---------------- conv We: transpose + split ----------------------------------
__global__ __launch_bounds__(256) void conv_We_kernel(const float* __restrict__ We)
{
    __shared__ float t[32][33];
    int e = blockIdx.z;
    int d0 = blockIdx.x * 32, h0 = blockIdx.y * 32;
    int tx = threadIdx.x, ty = threadIdx.y;   // (32, 8)
    const float* src = We + (size_t)e * D_DIM * D_DIM;
    #pragma unroll
    for (int i = 0; i < 4; ++i) {
        int r = ty + i * 8;
        t[r][tx] = src[(size_t)(d0 + r) * D_DIM + h0 + tx];
    }
    __syncthreads();
    #pragma unroll
    for (int i = 0; i < 4; ++i) {
        int r = ty + i * 8;
        float v = t[tx][r];
        __nv_bfloat16 hi = __float2bfloat16(v);
        __nv_bfloat16 lo = __float2bfloat16(v - __bfloat162float(hi));
        size_t off = ((size_t)e * D_DIM + h0 + r) * D_DIM + d0 + tx;
        g_Bhi[off] = hi;
        g_Blo[off] = lo;
    }
}

// ---------------- router (+ fused x hi/lo split) ------------------------------
__device__ __forceinline__ bool beats(float v, int i, float v2, int i2) {
    return (v > v2) || (v == v2 && i < i2);
}

__global__ __launch_bounds__(256) void router_kernel(
    const float* __restrict__ x, const float* __restrict__ Wr,
    const float* __restrict__ br)
{
    __shared__ float WrS[64 * 64];
    __shared__ float xS[8 * 64];
    int tid  = threadIdx.x;
    int warp = tid >> 5, lane = tid & 31;
    int token = blockIdx.x * 8 + warp;
    const float* xrow = x + (size_t)token * D_DIM;

    int ea = 2 * lane, eb = 2 * lane + 1;
    float acc0 = br[ea], acc1 = br[eb];

    for (int d0 = 0; d0 < D_DIM; d0 += 64) {
        __syncthreads();
        for (int i = tid; i < 64 * 16; i += 256) {
            int r = i >> 4, c4 = (i & 15) * 4;
            *(float4*)(WrS + r * 64 + c4) =
                *(const float4*)(Wr + (size_t)(d0 + r) * N_EXP + c4);
        }
        float xv0 = xrow[d0 + lane];
        float xv1 = xrow[d0 + lane + 32];
        xS[warp * 64 + lane]      = xv0;
        xS[warp * 64 + lane + 32] = xv1;
        // fused hi/lo split of x
        {
            __nv_bfloat16 h0 = __float2bfloat16(xv0);
            __nv_bfloat16 h1 = __float2bfloat16(xv1);
            __nv_bfloat16 l0 = __float2bfloat16(xv0 - __bfloat162float(h0));
            __nv_bfloat16 l1 = __float2bfloat16(xv1 - __bfloat162float(h1));
            size_t o = (size_t)token * D_DIM + d0 + lane;
            g_xhi[o] = h0; g_xhi[o + 32] = h1;
            g_xlo[o] = l0; g_xlo[o + 32] = l1;
        }
        __syncthreads();
        #pragma unroll
        for (int d = 0; d < 64; ++d) {
            float xv = xS[warp * 64 + d];
            float2 w = *(const float2*)(WrS + d * 64 + ea);
            acc0 = fmaf(xv, w.x, acc0);
            acc1 = fmaf(xv, w.y, acc1);
        }
    }

    float v1, v2; int i1, i2;
    if (beats(acc1, eb, acc0, ea)) { v1 = acc1; i1 = eb; v2 = acc0; i2 = ea; }
    else                           { v1 = acc0; i1 = ea; v2 = acc1; i2 = eb; }

    #pragma unroll
    for (int off = 16; off >= 1; off >>= 1) {
        float ov1 = __shfl_xor_sync(0xffffffffu, v1, off);
        int   oi1 = __shfl_xor_sync(0xffffffffu, i1, off);
        float ov2 = __shfl_xor_sync(0xffffffffu, v2, off);
        int   oi2 = __shfl_xor_sync(0xffffffffu, i2, off);
        if (beats(ov1, oi1, v1, i1)) {
            if (beats(ov2, oi2, v1, i1)) { v2 = ov2; i2 = oi2; }
            else                         { v2 = v1;  i2 = i1;  }
            v1 = ov1; i1 = oi1;
        } else {
            if (beats(ov1, oi1, v2, i2)) { v2 = ov1; i2 = oi1; }
        }
    }

    if (lane == 0) {
        float e1 = expf(v2 - v1);
        float inv = 1.0f / (1.0f + e1);
        g_topidx[2 * token]     = i1;
        g_topidx[2 * token + 1] = i2;
        g_gates [2 * token]     = inv;
        g_gates [2 * token + 1] = e1 * inv;
    }
}

// ---------------- fused dispatch: hist + scan + assign, one block -------------
// groups g = k*NCHUNK + chunk (k-major chunk order), 128 groups x 64 experts.
__global__ __launch_bounds__(1024) void dispatch_kernel()
{
    __shared__ int hist[128 * N_EXP];   // after scan: exclusive base (in-place),
                                        // then running allocator during assign
    int tid = threadIdx.x;

    for (int i = tid; i < 128 * N_EXP; i += 1024) hist[i] = 0;
    __syncthreads();

    // phase 1: histogram (order irrelevant)
    for (int i = tid; i < 2 * N_TOK; i += 1024) {
        int k = i >> 14, token = i & (N_TOK - 1);
        int e = g_topidx[token * 2 + k];
        int g = k * NCHUNK + (token >> 8);
        atomicAdd(&hist[g * N_EXP + e], 1);
    }
    __syncthreads();

    // phase 2: in-place exclusive scan per expert over g (k-major order)
    if (tid < N_EXP) {
        int run = 0;
        for (int g = 0; g < 128; ++g) {
            int v = hist[g * N_EXP + tid];
            hist[g * N_EXP + tid] = run;
            run += v;
        }
        g_cnt[tid] = run < CAPACITY ? run : CAPACITY;
    }
    __syncthreads();

    // phase 3: assign. one warp per group (4 groups per warp, sequential).
    int w = tid >> 5, lane = tid & 31;
    for (int q = 0; q < 4; ++q) {
        int g = w * 4 + q;
        int k = g >> 6, chunk = g & 63;
        #pragma unroll
        for (int it = 0; it < CHUNK / 32; ++it) {
            int token = chunk * CHUNK + it * 32 + lane;
            int e = g_topidx[token * 2 + k];
            unsigned m = __match_any_sync(0xffffffffu, e);
            int leader = __ffs(m) - 1;
            int rank = __popc(m & ((1u << lane) - 1u));
            int old = 0;
            if (lane == leader) old = atomicAdd(&hist[g * N_EXP + e], __popc(m));
            old = __shfl_sync(0xffffffffu, old, leader);
            int slot = old + rank;
            g_slot[token * 2 + k] = slot;
            if (slot < CAPACITY) g_toklist[e * CAPACITY + slot] = token * 2 + k;
        }
    }
}

// ---------------- mma.sync grouped expert GEMM --------------------------------
// 128x128 tile, Kchunk=32, split-bf16 3-pass with fragment reuse,
// 8 warps (4m x 2n), warp tile 32x64, 2-stage cp.async, 2 CTAs/SM.
#define PITCH_B 80
#define PLANE_BYTES (128 * PITCH_B)       // 10240
#define STAGE_BYTES (4 * PLANE_BYTES)     // 40960
#define SMEM_GEMM   (2 * STAGE_BYTES)     // 81920

__global__ __launch_bounds__(256, 2) void expert_gemm_mma()
{
    extern __shared__ char smem[];
    __shared__ int rowent[128];
    __shared__ int tokrow[128];

    int e = blockIdx.z;
    int cnt = g_cnt[e];
    int m0 = blockIdx.y * 128;
    if (m0 >= cnt) return;
    int n0 = blockIdx.x * 128;

    int tid = threadIdx.x;
    int lane = tid & 31;
    int wm = (tid >> 5) & 3;       // warp m quadrant
    int wn = tid >> 7;             // warp n half
    uint32_t sbase = smem_u32(smem);

    if (tid < 128) {
        int r = m0 + tid;
        int ent = (r < cnt) ? g_toklist[e * CAPACITY + r] : -1;
        rowent[tid] = ent;
        tokrow[tid] = (ent >= 0) ? (ent >> 1) : 0;
    }
    __syncthreads();

    const size_t bexp = (size_t)e * D_DIM * D_DIM;

    auto load_stage = [&](int stage, int c) {
        size_t koff = (size_t)c * KB;
        uint32_t sb = sbase + stage * STAGE_BYTES;
        #pragma unroll
        for (int j = 0; j < 8; ++j) {
            int idx = tid + j * 256;
            int isB = idx >> 10;
            int t = idx & 1023;
            int plane = t >> 9, u = t & 511, r = u >> 2, seg = u & 3;
            const __nv_bfloat16* src;
            if (!isB)
                src = (plane ? g_xlo : g_xhi)
                    + (size_t)tokrow[r] * D_DIM + koff + seg * 8;
            else
                src = (plane ? g_Blo : g_Bhi)
                    + bexp + (size_t)(n0 + r) * D_DIM + koff + seg * 8;
            uint32_t dst = sb + (isB ? 2 * PLANE_BYTES : 0)
                         + plane * PLANE_BYTES + r * PITCH_B + seg * 16;
            CP_ASYNC16(dst, src);
        }
    };

    int a_row = wm * 32 + (lane & 15);
    int a_colb = (lane >> 4) * 16;
    int b_row = wn * 64 + ((lane >> 4) & 1) * 8 + (lane & 7);
    int b_colb = ((lane >> 3) & 1) * 16;

    float acc[2][8][4];
    #pragma unroll
    for (int mt = 0; mt < 2; ++mt)
        #pragma unroll
        for (int nf = 0; nf < 8; ++nf)
            #pragma unroll
            for (int q = 0; q < 4; ++q) acc[mt][nf][q] = 0.f;

    load_stage(0, 0);
    CP_COMMIT();

    for (int c = 0; c < NCHUNKS_K; ++c) {
        if (c + 1 < NCHUNKS_K) {
            load_stage((c + 1) & 1, c + 1);
            CP_COMMIT();
            CP_WAIT1();
        } else {
            CP_WAIT0();
        }
        __syncthreads();

        uint32_t sb = sbase + (c & 1) * STAGE_BYTES;
        #pragma unroll
        for (int ks = 0; ks < 2; ++ks) {
            uint32_t ahi0[4], ahi1[4], alo0[4], alo1[4], bb[4][4];
            uint32_t ab = sb + a_colb + ks * 32;
            ldsm4(ahi0, ab + a_row * PITCH_B);
            ldsm4(ahi1, ab + (a_row + 16) * PITCH_B);
            uint32_t ab2 = ab + PLANE_BYTES;
            ldsm4(alo0, ab2 + a_row * PITCH_B);
            ldsm4(alo1, ab2 + (a_row + 16) * PITCH_B);

            uint32_t bbh = sb + 2 * PLANE_BYTES + b_colb + ks * 32;
            #pragma unroll
            for (int nt = 0; nt < 4; ++nt)
                ldsm4(bb[nt], bbh + (b_row + nt * 16) * PITCH_B);
            #pragma unroll
            for (int nt = 0; nt < 4; ++nt) {          // hi*hi + lo*hi
                mma16816(acc[0][2 * nt],     ahi0, &bb[nt][0]);
                mma16816(acc[0][2 * nt + 1], ahi0, &bb[nt][2]);
                mma16816(acc[1][2 * nt],     ahi1, &bb[nt][0]);
                mma16816(acc[1][2 * nt + 1], ahi1, &bb[nt][2]);
                mma16816(acc[0][2 * nt],     alo0, &bb[nt][0]);
                mma16816(acc[0][2 * nt + 1], alo0, &bb[nt][2]);
                mma16816(acc[1][2 * nt],     alo1, &bb[nt][0]);
                mma16816(acc[1][2 * nt + 1], alo1, &bb[nt][2]);
            }
            uint32_t bbl = bbh + PLANE_BYTES;
            #pragma unroll
            for (int nt = 0; nt < 4; ++nt)
                ldsm4(bb[nt], bbl + (b_row + nt * 16) * PITCH_B);
            #pragma unroll
            for (int nt = 0; nt < 4; ++nt) {          // hi*lo
                mma16816(acc[0][2 * nt],     ahi0, &bb[nt][0]);
                mma16816(acc[0][2 * nt + 1], ahi0, &bb[nt][2]);
                mma16816(acc[1][2 * nt],     ahi1, &bb[nt][0]);
                mma16816(acc[1][2 * nt + 1], ahi1, &bb[nt][2]);
            }
        }
        __syncthreads();
    }

    // epilogue: relu + scatter
    int colb = (lane & 3) * 2;
    #pragma unroll
    for (int mt = 0; mt < 2; ++mt) {
        #pragma unroll
        for (int h = 0; h < 2; ++h) {
            int row = wm * 32 + mt * 16 + (lane >> 2) + h * 8;
            int ent = rowent[row];
            if (ent < 0) continue;
            float* yrow = g_ybuf + (size_t)ent * D_DIM + n0 + wn * 64 + colb;
            #pragma unroll
            for (int nf = 0; nf < 8; ++nf) {
                float2 o;
                o.x = fmaxf(acc[mt][nf][h * 2],     0.f);
                o.y = fmaxf(acc[mt][nf][h * 2 + 1], 0.f);
                *(float2*)(yrow + nf * 8) = o;
            }
        }
    }
}

// ---------------- combine -----------------------------------------------------
__global__ __launch_bounds__(256) void combine_kernel(float* __restrict__ out)
{
    int t = blockIdx.x;
    int d = threadIdx.x * 4;
    int s0 = g_slot[2 * t], s1 = g_slot[2 * t + 1];
    float g0 = g_gates[2 * t], g1 = g_gates[2 * t + 1];
    float4 acc = make_float4(0.f, 0.f, 0.f, 0.f);
    if (s0 < CAPACITY) {
        float4 v = *(const float4*)(g_ybuf + (size_t)(2 * t) * D_DIM + d);
        acc.x += g0 * v.x; acc.y += g0 * v.y; acc.z += g0 * v.z; acc.w += g0 * v.w;
    }
    if (s1 < CAPACITY) {
        float4 v = *(const float4*)(g_ybuf + (size_t)(2 * t + 1) * D_DIM + d);
        acc.x += g1 * v.x; acc.y += g1 * v.y; acc.z += g1 * v.z; acc.w += g1 * v.w;
    }
    *(float4*)(out + (size_t)t * D_DIM + d) = acc;
}

// ---------------- launch ------------------------------------------------------
extern "C" void kernel_launch(void* const* d_in, const int* in_sizes, int n_in,
                              void* d_out, int out_size)
{
    const float* x  = (const float*)d_in[0];
    const float* Wr = (const float*)d_in[1];
    const float* br = (const float*)d_in[2];
    const float* We = (const float*)d_in[3];
    float* out = (float*)d_out;
    (void)in_sizes; (void)n_in; (void)out_size;

    static bool attr_done = false;
    if (!attr_done) {
        cudaFuncSetAttribute(expert_gemm_mma,
                             cudaFuncAttributeMaxDynamicSharedMemorySize,
                             SMEM_GEMM);
        attr_done = true;
    }

    router_kernel<<<N_TOK / 8, 256>>>(x, Wr, br);          // 0
    dim3 wg(32, 32, 64);
    conv_We_kernel<<<wg, dim3(32, 8)>>>(We);               // 1
    dispatch_kernel<<<1, 1024>>>();                        // 2
    dim3 gg(D_DIM / 128, (CAPACITY + 127) / 128, N_EXP);
    expert_gemm_mma<<<gg, 256, SMEM_GEMM>>>();             // 3  <- profiled
    combine_kernel<<<N_TOK, 256>>>(out);                   // 4
}